// round 15
// baseline (speedup 1.0000x reference)
#include <cuda_runtime.h>
#include <cuda_bf16.h>
#include <cstdint>

#define NN 100000
#define EE 1600000
#define GG 128
#define IND 329
#define NEG 0.2f
#define NB 98          // ceil(NN/1024)

// ---------------- device scratch (no allocation allowed) ----------------
__device__ __align__(256) __nv_bfloat16 g_xp[(size_t)NN * 256];   // 51.2 MB bf16 features [N][H*C]
__device__ __align__(256) float g_asrc[NN * 4];
__device__ __align__(256) float g_adst[NN * 4];
__device__ __align__(256) float g_ex[(size_t)EE * 4];             // 25.6 MB per-edge exp values
__device__ __align__(256) int   g_srcs[EE];                       // 6.4 MB dst-binned src list
__device__ __align__(256) int   g_deg[NN];
__device__ __align__(256) int   g_off[NN + 1];
__device__ __align__(256) int   g_cursor[NN];
__device__ __align__(256) int   g_bsum[NB];
__device__ __align__(256) int   g_bsum2[NB];
__device__ __align__(256) float g_pool[GG * 64];
__device__ __align__(256) float g_cnt[GG];
__device__ int g_e64;   // 1 if edge_index is int64, 0 if int32
__device__ int g_b64;   // 1 if batch is int64, 0 if int32

// ---------------- small helpers ----------------
__device__ __forceinline__ float2 bf2f(unsigned u) {
    __nv_bfloat162 b = *reinterpret_cast<const __nv_bfloat162*>(&u);
    return __bfloat1622float2(b);
}
__device__ __forceinline__ float lrelu(float x) { return x > 0.f ? x : NEG * x; }
__device__ __forceinline__ void red4(float* p, float a, float b, float c, float d) {
    asm volatile("red.global.add.v4.f32 [%0], {%1,%2,%3,%4};"
                 :: "l"(p), "f"(a), "f"(b), "f"(c), "f"(d) : "memory");
}
__device__ __forceinline__ unsigned f2tf32(float v) {
    unsigned u;
    asm("cvt.rna.tf32.f32 %0, %1;" : "=r"(u) : "f"(v));
    return u;
}
__device__ __forceinline__ void mma_tf32(float& c0, float& c1, float& c2, float& c3,
                                         unsigned a0, unsigned a1, unsigned a2, unsigned a3,
                                         unsigned b0, unsigned b1) {
    asm volatile("mma.sync.aligned.m16n8k8.row.col.f32.tf32.tf32.f32 "
                 "{%0,%1,%2,%3}, {%4,%5,%6,%7}, {%8,%9}, {%0,%1,%2,%3};"
                 : "+f"(c0), "+f"(c1), "+f"(c2), "+f"(c3)
                 : "r"(a0), "r"(a1), "r"(a2), "r"(a3), "r"(b0), "r"(b1));
}
// dtype-flexible index load, clamped to [0, lim-1]
__device__ __forceinline__ int ldidx(const void* p, long long i, int is64, int lim) {
    long long v = is64 ? ((const long long*)p)[i] : (long long)((const int*)p)[i];
    if (v < 0) v = 0;
    if (v >= lim) v = lim - 1;
    return (int)v;
}
// accumulate 8 bf16 cols scaled by a into acc[0..7]
__device__ __forceinline__ void accum8(float* acc, uint4 v, float a) {
    float2 p;
    p = bf2f(v.x); acc[0] += a * p.x; acc[1] += a * p.y;
    p = bf2f(v.y); acc[2] += a * p.x; acc[3] += a * p.y;
    p = bf2f(v.z); acc[4] += a * p.x; acc[5] += a * p.y;
    p = bf2f(v.w); acc[6] += a * p.x; acc[7] += a * p.y;
}

// ---------------- K-1: dtype detector (int32 vs int64) ----------------
__global__ void k_detect(const int* __restrict__ ei_raw, const int* __restrict__ bat_raw) {
    __shared__ int nz_e, nz_b;
    int t = threadIdx.x;  // 256 threads
    if (t == 0) { nz_e = 0; nz_b = 0; }
    __syncthreads();
    if (ei_raw[2 * t + 1] != 0) atomicOr(&nz_e, 1);
    if (bat_raw[NN - 1 - 2 * t] != 0) atomicOr(&nz_b, 1);
    __syncthreads();
    if (t == 0) { g_e64 = nz_e ? 0 : 1; g_b64 = nz_b ? 0 : 1; }
}

// ---------------- K0: zero degree table + pool accumulators ----------------
__global__ void k_zero() {
    int i = blockIdx.x * blockDim.x + threadIdx.x;
    int stride = gridDim.x * blockDim.x;
    for (int j = i; j < NN; j += stride) g_deg[j] = 0;
    if (i < GG * 64) g_pool[i] = 0.f;
    if (i < GG) g_cnt[i] = 0.f;
}

// ---------------- CSR build: histogram ----------------
__global__ void k_hist(const void* __restrict__ ei) {
    int e = blockIdx.x * 256 + threadIdx.x;
    if (e >= EE) return;
    int d = ldidx(ei, (long long)EE + e, g_e64, NN);
    atomicAdd(&g_deg[d], 1);
}

// ---------------- CSR build: 3-phase multi-block exclusive scan ----------------
__global__ __launch_bounds__(1024) void k_scanA() {
    __shared__ int wsum[32];
    int b = blockIdx.x, tid = threadIdx.x;
    int lane = tid & 31, wid = tid >> 5;
    int idx = b * 1024 + tid;
    int v = (idx < NN) ? g_deg[idx] : 0;
    int inc = v;
#pragma unroll
    for (int off = 1; off < 32; off <<= 1) {
        int t = __shfl_up_sync(0xffffffffu, inc, off);
        if (lane >= off) inc += t;
    }
    if (lane == 31) wsum[wid] = inc;
    __syncthreads();
    if (wid == 0) {
        int x = wsum[lane];
        int iw = x;
#pragma unroll
        for (int off = 1; off < 32; off <<= 1) {
            int t = __shfl_up_sync(0xffffffffu, iw, off);
            if (lane >= off) iw += t;
        }
        wsum[lane] = iw - x;   // exclusive warp offset
    }
    __syncthreads();
    int excl = inc - v + wsum[wid];
    if (idx < NN) g_off[idx] = excl;         // block-local exclusive
    if (tid == 1023) g_bsum[b] = excl + v;   // block total
}

__global__ void k_scanB() {
    __shared__ int wsum[4];
    int t = threadIdx.x;   // 128 threads
    int lane = t & 31, wid = t >> 5;
    int v = (t < NB) ? g_bsum[t] : 0;
    int inc = v;
#pragma unroll
    for (int off = 1; off < 32; off <<= 1) {
        int x = __shfl_up_sync(0xffffffffu, inc, off);
        if (lane >= off) inc += x;
    }
    if (lane == 31) wsum[wid] = inc;
    __syncthreads();
    if (t == 0) {
        int run = 0;
#pragma unroll
        for (int i = 0; i < 4; i++) { int x = wsum[i]; wsum[i] = run; run += x; }
    }
    __syncthreads();
    if (t < NB) g_bsum2[t] = inc - v + wsum[wid];
}

__global__ __launch_bounds__(1024) void k_scanC() {
    int b = blockIdx.x, tid = threadIdx.x;
    int idx = b * 1024 + tid;
    if (idx < NN) {
        int o = g_off[idx] + g_bsum2[b];
        g_off[idx] = o;
        g_cursor[idx] = o;
    }
    if (idx == 0) g_off[NN] = EE;
}

// ---------------- CSR build: scatter srcs into dst bins ----------------
__global__ void k_scatter(const void* __restrict__ ei) {
    int e = blockIdx.x * 256 + threadIdx.x;
    if (e >= EE) return;
    int f = g_e64;
    int s = ldidx(ei, e, f, NN);
    int d = ldidx(ei, (long long)EE + e, f, NN);
    int p = atomicAdd(&g_cursor[d], 1);
    g_srcs[p] = s;
}

// ---------------- K1: TF32 tensor-core GEMM  xp = x @ W  (bf16 store)
//                  + fused attention dots a_src/a_dst from fp32 accumulators ----------------
#define SSTRIDE 136
__global__ __launch_bounds__(256) void k_gemm(const float* __restrict__ x,
                                              const float* __restrict__ W,
                                              const float* __restrict__ att_src,
                                              const float* __restrict__ att_dst) {
    __shared__ unsigned As[16][SSTRIDE];
    __shared__ unsigned Bs[16][SSTRIDE];
    int tid = threadIdx.x;
    int lane = tid & 31;
    int wid = tid >> 5;
    int warpM = wid & 3;
    int warpN = wid >> 2;
    int rowBase = blockIdx.y * 128;
    int colBase = blockIdx.x * 128;
    int p = lane >> 2;
    int q = lane & 3;

    float acc[2][8][4];
#pragma unroll
    for (int i = 0; i < 2; i++)
#pragma unroll
        for (int j = 0; j < 8; j++)
#pragma unroll
            for (int r = 0; r < 4; r++) acc[i][j][r] = 0.f;

    int am = tid >> 1;
    int aklo = (tid & 1) * 8;
    int arow = rowBase + am;
    int bkk = tid >> 4;
    int bc = (tid & 15) * 8;

    for (int kt = 0; kt < 21; kt++) {
        int k0 = kt * 16;
        float av[8];
#pragma unroll
        for (int i = 0; i < 8; i++) {
            int kk = k0 + aklo + i;
            av[i] = (arow < NN && kk < IND) ? x[(size_t)arow * IND + kk] : 0.f;
        }
        float4 bv0 = make_float4(0.f, 0.f, 0.f, 0.f), bv1 = bv0;
        {
            int kk = k0 + bkk;
            if (kk < IND) {
                bv0 = *(const float4*)&W[(size_t)kk * 256 + colBase + bc];
                bv1 = *(const float4*)&W[(size_t)kk * 256 + colBase + bc + 4];
            }
        }
        __syncthreads();
#pragma unroll
        for (int i = 0; i < 8; i++) As[aklo + i][am] = f2tf32(av[i]);
        Bs[bkk][bc + 0] = f2tf32(bv0.x); Bs[bkk][bc + 1] = f2tf32(bv0.y);
        Bs[bkk][bc + 2] = f2tf32(bv0.z); Bs[bkk][bc + 3] = f2tf32(bv0.w);
        Bs[bkk][bc + 4] = f2tf32(bv1.x); Bs[bkk][bc + 5] = f2tf32(bv1.y);
        Bs[bkk][bc + 6] = f2tf32(bv1.z); Bs[bkk][bc + 7] = f2tf32(bv1.w);
        __syncthreads();

#pragma unroll
        for (int ks = 0; ks < 16; ks += 8) {
            unsigned a[2][4];
#pragma unroll
            for (int mt = 0; mt < 2; mt++) {
                int m0 = warpM * 32 + mt * 16;
                a[mt][0] = As[ks + q][m0 + p];
                a[mt][1] = As[ks + q][m0 + p + 8];
                a[mt][2] = As[ks + q + 4][m0 + p];
                a[mt][3] = As[ks + q + 4][m0 + p + 8];
            }
#pragma unroll
            for (int nt = 0; nt < 8; nt++) {
                int n0 = warpN * 64 + nt * 8;
                unsigned b0 = Bs[ks + q][n0 + p];
                unsigned b1 = Bs[ks + q + 4][n0 + p];
#pragma unroll
                for (int mt = 0; mt < 2; mt++)
                    mma_tf32(acc[mt][nt][0], acc[mt][nt][1], acc[mt][nt][2], acc[mt][nt][3],
                             a[mt][0], a[mt][1], a[mt][2], a[mt][3], b0, b1);
            }
        }
    }

    // bf16 store epilogue
#pragma unroll
    for (int mt = 0; mt < 2; mt++) {
        int r0 = rowBase + warpM * 32 + mt * 16 + p;
        int r1 = r0 + 8;
#pragma unroll
        for (int nt = 0; nt < 8; nt++) {
            int col = colBase + warpN * 64 + nt * 8 + 2 * q;
            if (r0 < NN) {
                __nv_bfloat162 v = __floats2bfloat162_rn(acc[mt][nt][0], acc[mt][nt][1]);
                *(__nv_bfloat162*)&g_xp[(size_t)r0 * 256 + col] = v;
            }
            if (r1 < NN) {
                __nv_bfloat162 v = __floats2bfloat162_rn(acc[mt][nt][2], acc[mt][nt][3]);
                *(__nv_bfloat162*)&g_xp[(size_t)r1 * 256 + col] = v;
            }
        }
    }

    // fused attention dots: this warp's 64-col slab is exactly head h.
    int h = blockIdx.x * 2 + warpN;
    float a_s0[8], a_s1[8], a_d0[8], a_d1[8];
#pragma unroll
    for (int nt = 0; nt < 8; nt++) {
        int cb = h * 64 + nt * 8 + 2 * q;
        a_s0[nt] = att_src[cb]; a_s1[nt] = att_src[cb + 1];
        a_d0[nt] = att_dst[cb]; a_d1[nt] = att_dst[cb + 1];
    }
#pragma unroll
    for (int mt = 0; mt < 2; mt++) {
        float sdA = 0.f, ddA = 0.f, sdB = 0.f, ddB = 0.f;
#pragma unroll
        for (int nt = 0; nt < 8; nt++) {
            sdA += acc[mt][nt][0] * a_s0[nt] + acc[mt][nt][1] * a_s1[nt];
            ddA += acc[mt][nt][0] * a_d0[nt] + acc[mt][nt][1] * a_d1[nt];
            sdB += acc[mt][nt][2] * a_s0[nt] + acc[mt][nt][3] * a_s1[nt];
            ddB += acc[mt][nt][2] * a_d0[nt] + acc[mt][nt][3] * a_d1[nt];
        }
#pragma unroll
        for (int off = 1; off < 4; off <<= 1) {
            sdA += __shfl_xor_sync(0xffffffffu, sdA, off);
            ddA += __shfl_xor_sync(0xffffffffu, ddA, off);
            sdB += __shfl_xor_sync(0xffffffffu, sdB, off);
            ddB += __shfl_xor_sync(0xffffffffu, ddB, off);
        }
        if (q == 0) {
            int rA = rowBase + warpM * 32 + mt * 16 + p;
            int rB = rA + 8;
            if (rA < NN) { g_asrc[rA * 4 + h] = sdA; g_adst[rA * 4 + h] = ddA; }
            if (rB < NN) { g_asrc[rB * 4 + h] = sdB; g_adst[rB * 4 + h] = ddB; }
        }
    }
}

// ---------------- K3: fused per-node softmax + aggregation + finalize + pool ----------------
// one warp per node; loop2 lane = (g, j): g = edge group (4 edges in flight),
// j = 16B segment of the 512B xp row. Each lane accumulates head-summed cols 8j..8j+7.
__global__ __launch_bounds__(256) void k_node_csr(const void* __restrict__ batch,
                                                  const float* __restrict__ bias) {
    int n = (blockIdx.x * 256 + threadIdx.x) >> 5;
    int lane = threadIdx.x & 31;
    if (n >= NN) return;
    int g = lane >> 3;     // 0..3 edge group
    int j = lane & 7;      // 0..7 row segment
    float4 ad = *(const float4*)&g_adst[n * 4];
    float4 an = *(const float4*)&g_asrc[n * 4];
    float se0 = __expf(lrelu(an.x + ad.x));
    float se1 = __expf(lrelu(an.y + ad.y));
    float se2 = __expf(lrelu(an.z + ad.z));
    float se3 = __expf(lrelu(an.w + ad.w));
    int o0 = g_off[n], o1 = g_off[n + 1];

    // loop1: per-edge exps (stored, coalesced) + denominator (lane-strided)
    float d0 = 0.f, d1 = 0.f, d2 = 0.f, d3 = 0.f;
    for (int e = o0 + lane; e < o1; e += 32) {
        int s = g_srcs[e];
        float4 as = *(const float4*)&g_asrc[s * 4];
        float e0 = __expf(lrelu(as.x + ad.x));
        float e1 = __expf(lrelu(as.y + ad.y));
        float e2 = __expf(lrelu(as.z + ad.z));
        float e3 = __expf(lrelu(as.w + ad.w));
        *(float4*)&g_ex[(size_t)e * 4] = make_float4(e0, e1, e2, e3);
        d0 += e0; d1 += e1; d2 += e2; d3 += e3;
    }
#pragma unroll
    for (int off = 16; off > 0; off >>= 1) {
        d0 += __shfl_xor_sync(0xffffffffu, d0, off);
        d1 += __shfl_xor_sync(0xffffffffu, d1, off);
        d2 += __shfl_xor_sync(0xffffffffu, d2, off);
        d3 += __shfl_xor_sync(0xffffffffu, d3, off);
    }
    float inv0 = __frcp_rn(d0 + se0);
    float inv1 = __frcp_rn(d1 + se1);
    float inv2 = __frcp_rn(d2 + se2);
    float inv3 = __frcp_rn(d3 + se3);

    const uint4* xp4 = (const uint4*)g_xp;   // 16B segments; row r = 32 segments
    float acc[8];
#pragma unroll
    for (int i = 0; i < 8; i++) acc[i] = 0.f;

    // self-loop (every group does 1/4 of nothing extra: only group contributes once —
    // do it in group 0 only to avoid 4x duplication)
    if (g == 0) {
        size_t rb = (size_t)n * 32;
        accum8(acc, xp4[rb + j],      se0 * inv0);
        accum8(acc, xp4[rb + 8 + j],  se1 * inv1);
        accum8(acc, xp4[rb + 16 + j], se2 * inv2);
        accum8(acc, xp4[rb + 24 + j], se3 * inv3);
    }

    // loop2: 4 edges in flight (one per group), vectorized LDG.128 row reads
    for (int base = o0; base < o1; base += 4) {
        int eg = base + g;
        bool valid = eg < o1;
        int s = valid ? g_srcs[eg] : n;
        float4 ex = valid ? *(const float4*)&g_ex[(size_t)eg * 4]
                          : make_float4(0.f, 0.f, 0.f, 0.f);
        size_t rb = (size_t)s * 32;
        uint4 v0 = xp4[rb + j];
        uint4 v1 = xp4[rb + 8 + j];
        uint4 v2 = xp4[rb + 16 + j];
        uint4 v3 = xp4[rb + 24 + j];
        accum8(acc, v0, ex.x * inv0);
        accum8(acc, v1, ex.y * inv1);
        accum8(acc, v2, ex.z * inv2);
        accum8(acc, v3, ex.w * inv3);
    }

    // fold the 4 groups
#pragma unroll
    for (int i = 0; i < 8; i++) {
        acc[i] += __shfl_xor_sync(0xffffffffu, acc[i], 8);
        acc[i] += __shfl_xor_sync(0xffffffffu, acc[i], 16);
    }

    if (g == 0) {
        int cb = j * 8;
        float r[8];
#pragma unroll
        for (int i = 0; i < 8; i++)
            r[i] = fmaxf(acc[i] * 0.25f + bias[cb + i], 0.f);
        int gph = ldidx(batch, n, g_b64, GG);
        float* dst = &g_pool[gph * 64 + cb];
        red4(dst, r[0], r[1], r[2], r[3]);
        red4(dst + 4, r[4], r[5], r[6], r[7]);
        if (j == 0) atomicAdd(&g_cnt[gph], 1.0f);
    }
}

// ---------------- K5: per-graph mean + MLP head + sigmoid ----------------
__global__ void k_head(const float* __restrict__ w1, const float* __restrict__ b1,
                       const float* __restrict__ w2, const float* __restrict__ b2,
                       float* __restrict__ out) {
    __shared__ float w1s[64 * 64];
    __shared__ float b1s[64];
    __shared__ float w2s[64];
    int t = threadIdx.x;
    for (int i = t; i < 64 * 64; i += 128) w1s[i] = w1[i];
    if (t < 64) { b1s[t] = b1[t]; w2s[t] = w2[t]; }
    __syncthreads();
    if (t < GG) {
        float cnt = fmaxf(g_cnt[t], 1.0f);
        float inv = 1.0f / cnt;
        float gv[64];
#pragma unroll
        for (int c = 0; c < 64; c++) gv[c] = g_pool[t * 64 + c] * inv;
        float z = b2[0];
        for (int k = 0; k < 64; k++) {
            float a = b1s[k];
#pragma unroll
            for (int c = 0; c < 64; c++) a += gv[c] * w1s[c * 64 + k];
            a = fmaxf(a, 0.f);
            z += a * w2s[k];
        }
        out[t] = 1.0f / (1.0f + expf(-z));
    }
}

// ---------------- launcher (gemm moved to launch #4 so ncu profiles it) ----------------
extern "C" void kernel_launch(void* const* d_in, const int* in_sizes, int n_in,
                              void* d_out, int out_size) {
    const float* x       = (const float*)d_in[0];
    const float* W       = (const float*)d_in[1];
    const float* att_src = (const float*)d_in[2];
    const float* att_dst = (const float*)d_in[3];
    const float* bias    = (const float*)d_in[4];
    const float* w1      = (const float*)d_in[5];
    const float* b1      = (const float*)d_in[6];
    const float* w2      = (const float*)d_in[7];
    const float* b2      = (const float*)d_in[8];
    const void*  ei      = d_in[9];
    const void*  bat     = d_in[10];

    k_detect<<<1, 256>>>((const int*)ei, (const int*)bat);
    k_zero<<<200, 512>>>();
    k_hist<<<(EE + 255) / 256, 256>>>(ei);
    dim3 gg(2, (NN + 127) / 128);
    k_gemm<<<gg, 256>>>(x, W, att_src, att_dst);   // launch #4 -> profiled
    k_scanA<<<NB, 1024>>>();
    k_scanB<<<1, 128>>>();
    k_scanC<<<NB, 1024>>>();
    k_scatter<<<(EE + 255) / 256, 256>>>(ei);
    k_node_csr<<<(NN * 32 + 255) / 256, 256>>>(bat, bias);
    k_head<<<1, 128>>>(w1, b1, w2, b2, (float*)d_out);
}

// round 16
// speedup vs baseline: 1.2656x; 1.2656x over previous
#include <cuda_runtime.h>
#include <cuda_bf16.h>
#include <cstdint>

#define NN 100000
#define EE 1600000
#define GG 128
#define IND 329
#define NEG 0.2f
#define NB 98          // ceil(NN/1024)

// ---------------- device scratch (no allocation allowed) ----------------
__device__ __align__(256) __nv_bfloat16 g_xp[(size_t)NN * 256];   // 51.2 MB bf16 features [N][H*C]
__device__ __align__(256) float g_asrc[NN * 4];
__device__ __align__(256) float g_adst[NN * 4];
__device__ __align__(256) float g_ex[(size_t)EE * 4];             // 25.6 MB per-edge exp values
__device__ __align__(256) int   g_srcs[EE];                       // 6.4 MB dst-binned src list
__device__ __align__(256) int   g_deg[NN];
__device__ __align__(256) int   g_off[NN + 1];
__device__ __align__(256) int   g_cursor[NN];
__device__ __align__(256) int   g_bsum[NB];
__device__ __align__(256) int   g_bsum2[NB];
__device__ __align__(256) float g_pool[GG * 64];
__device__ __align__(256) float g_cnt[GG];
__device__ int g_e64;   // 1 if edge_index is int64, 0 if int32
__device__ int g_b64;   // 1 if batch is int64, 0 if int32

// ---------------- small helpers ----------------
__device__ __forceinline__ float2 bf2f(unsigned u) {
    __nv_bfloat162 b = *reinterpret_cast<const __nv_bfloat162*>(&u);
    return __bfloat1622float2(b);
}
__device__ __forceinline__ float lrelu(float x) { return x > 0.f ? x : NEG * x; }
__device__ __forceinline__ void red2(float* p, float a, float b) {
    asm volatile("red.global.add.v2.f32 [%0], {%1,%2};"
                 :: "l"(p), "f"(a), "f"(b) : "memory");
}
__device__ __forceinline__ unsigned f2tf32(float v) {
    unsigned u;
    asm("cvt.rna.tf32.f32 %0, %1;" : "=r"(u) : "f"(v));
    return u;
}
__device__ __forceinline__ void mma_tf32(float& c0, float& c1, float& c2, float& c3,
                                         unsigned a0, unsigned a1, unsigned a2, unsigned a3,
                                         unsigned b0, unsigned b1) {
    asm volatile("mma.sync.aligned.m16n8k8.row.col.f32.tf32.tf32.f32 "
                 "{%0,%1,%2,%3}, {%4,%5,%6,%7}, {%8,%9}, {%0,%1,%2,%3};"
                 : "+f"(c0), "+f"(c1), "+f"(c2), "+f"(c3)
                 : "r"(a0), "r"(a1), "r"(a2), "r"(a3), "r"(b0), "r"(b1));
}
// dtype-flexible index load, clamped to [0, lim-1]
__device__ __forceinline__ int ldidx(const void* p, long long i, int is64, int lim) {
    long long v = is64 ? ((const long long*)p)[i] : (long long)((const int*)p)[i];
    if (v < 0) v = 0;
    if (v >= lim) v = lim - 1;
    return (int)v;
}

// ---------------- K-1: dtype detector (int32 vs int64) ----------------
__global__ void k_detect(const int* __restrict__ ei_raw, const int* __restrict__ bat_raw) {
    __shared__ int nz_e, nz_b;
    int t = threadIdx.x;  // 256 threads
    if (t == 0) { nz_e = 0; nz_b = 0; }
    __syncthreads();
    if (ei_raw[2 * t + 1] != 0) atomicOr(&nz_e, 1);
    if (bat_raw[NN - 1 - 2 * t] != 0) atomicOr(&nz_b, 1);
    __syncthreads();
    if (t == 0) { g_e64 = nz_e ? 0 : 1; g_b64 = nz_b ? 0 : 1; }
}

// ---------------- K0: zero degree table + pool accumulators ----------------
__global__ void k_zero() {
    int i = blockIdx.x * blockDim.x + threadIdx.x;
    int stride = gridDim.x * blockDim.x;
    for (int j = i; j < NN; j += stride) g_deg[j] = 0;
    if (i < GG * 64) g_pool[i] = 0.f;
    if (i < GG) g_cnt[i] = 0.f;
}

// ---------------- CSR build: histogram ----------------
__global__ void k_hist(const void* __restrict__ ei) {
    int e = blockIdx.x * 256 + threadIdx.x;
    if (e >= EE) return;
    int d = ldidx(ei, (long long)EE + e, g_e64, NN);
    atomicAdd(&g_deg[d], 1);
}

// ---------------- CSR build: 3-phase multi-block exclusive scan ----------------
__global__ __launch_bounds__(1024) void k_scanA() {
    __shared__ int wsum[32];
    int b = blockIdx.x, tid = threadIdx.x;
    int lane = tid & 31, wid = tid >> 5;
    int idx = b * 1024 + tid;
    int v = (idx < NN) ? g_deg[idx] : 0;
    int inc = v;
#pragma unroll
    for (int off = 1; off < 32; off <<= 1) {
        int t = __shfl_up_sync(0xffffffffu, inc, off);
        if (lane >= off) inc += t;
    }
    if (lane == 31) wsum[wid] = inc;
    __syncthreads();
    if (wid == 0) {
        int x = wsum[lane];
        int iw = x;
#pragma unroll
        for (int off = 1; off < 32; off <<= 1) {
            int t = __shfl_up_sync(0xffffffffu, iw, off);
            if (lane >= off) iw += t;
        }
        wsum[lane] = iw - x;   // exclusive warp offset
    }
    __syncthreads();
    int excl = inc - v + wsum[wid];
    if (idx < NN) g_off[idx] = excl;         // block-local exclusive
    if (tid == 1023) g_bsum[b] = excl + v;   // block total
}

__global__ void k_scanB() {
    __shared__ int wsum[4];
    int t = threadIdx.x;   // 128 threads
    int lane = t & 31, wid = t >> 5;
    int v = (t < NB) ? g_bsum[t] : 0;
    int inc = v;
#pragma unroll
    for (int off = 1; off < 32; off <<= 1) {
        int x = __shfl_up_sync(0xffffffffu, inc, off);
        if (lane >= off) inc += x;
    }
    if (lane == 31) wsum[wid] = inc;
    __syncthreads();
    if (t == 0) {
        int run = 0;
#pragma unroll
        for (int i = 0; i < 4; i++) { int x = wsum[i]; wsum[i] = run; run += x; }
    }
    __syncthreads();
    if (t < NB) g_bsum2[t] = inc - v + wsum[wid];
}

__global__ __launch_bounds__(1024) void k_scanC() {
    int b = blockIdx.x, tid = threadIdx.x;
    int idx = b * 1024 + tid;
    if (idx < NN) {
        int o = g_off[idx] + g_bsum2[b];
        g_off[idx] = o;
        g_cursor[idx] = o;
    }
    if (idx == 0) g_off[NN] = EE;
}

// ---------------- CSR build: scatter srcs into dst bins ----------------
__global__ void k_scatter(const void* __restrict__ ei) {
    int e = blockIdx.x * 256 + threadIdx.x;
    if (e >= EE) return;
    int f = g_e64;
    int s = ldidx(ei, e, f, NN);
    int d = ldidx(ei, (long long)EE + e, f, NN);
    int p = atomicAdd(&g_cursor[d], 1);
    g_srcs[p] = s;
}

// ---------------- K1: TF32 tensor-core GEMM  xp = x @ W  (bf16 store)
// Double-buffered smem + register prefetch: tile kt+1's LDGs issue BEFORE the
// MMA phase of tile kt, so global latency overlaps compute. ONE sync per tile.
//                  + fused attention dots a_src/a_dst from fp32 accumulators ----------------
#define SSTRIDE 136
__global__ __launch_bounds__(256, 2) void k_gemm(const float* __restrict__ x,
                                                 const float* __restrict__ W,
                                                 const float* __restrict__ att_src,
                                                 const float* __restrict__ att_dst) {
    __shared__ unsigned As[2][16][SSTRIDE];
    __shared__ unsigned Bs[2][16][SSTRIDE];
    int tid = threadIdx.x;
    int lane = tid & 31;
    int wid = tid >> 5;
    int warpM = wid & 3;
    int warpN = wid >> 2;
    int rowBase = blockIdx.y * 128;
    int colBase = blockIdx.x * 128;
    int p = lane >> 2;
    int q = lane & 3;

    float acc[2][8][4];
#pragma unroll
    for (int i = 0; i < 2; i++)
#pragma unroll
        for (int j = 0; j < 8; j++)
#pragma unroll
            for (int r = 0; r < 4; r++) acc[i][j][r] = 0.f;

    int am = tid >> 1;
    int aklo = (tid & 1) * 8;
    int arow = rowBase + am;
    int bkk = tid >> 4;
    int bc = (tid & 15) * 8;

    float avr[8];
    float4 bv0, bv1;

    // prologue: load + store tile 0
#pragma unroll
    for (int i = 0; i < 8; i++) {
        int kk = aklo + i;
        avr[i] = (arow < NN && kk < IND) ? x[(size_t)arow * IND + kk] : 0.f;
    }
    bv0 = make_float4(0.f, 0.f, 0.f, 0.f); bv1 = bv0;
    if (bkk < IND) {
        bv0 = *(const float4*)&W[(size_t)bkk * 256 + colBase + bc];
        bv1 = *(const float4*)&W[(size_t)bkk * 256 + colBase + bc + 4];
    }
#pragma unroll
    for (int i = 0; i < 8; i++) As[0][aklo + i][am] = f2tf32(avr[i]);
    Bs[0][bkk][bc + 0] = f2tf32(bv0.x); Bs[0][bkk][bc + 1] = f2tf32(bv0.y);
    Bs[0][bkk][bc + 2] = f2tf32(bv0.z); Bs[0][bkk][bc + 3] = f2tf32(bv0.w);
    Bs[0][bkk][bc + 4] = f2tf32(bv1.x); Bs[0][bkk][bc + 5] = f2tf32(bv1.y);
    Bs[0][bkk][bc + 6] = f2tf32(bv1.z); Bs[0][bkk][bc + 7] = f2tf32(bv1.w);
    __syncthreads();

    for (int kt = 0; kt < 21; kt++) {
        int cur = kt & 1;
        bool hasNext = (kt + 1 < 21);
        // prefetch tile kt+1 into registers (overlaps the MMA phase below)
        if (hasNext) {
            int k0 = (kt + 1) * 16;
#pragma unroll
            for (int i = 0; i < 8; i++) {
                int kk = k0 + aklo + i;
                avr[i] = (arow < NN && kk < IND) ? x[(size_t)arow * IND + kk] : 0.f;
            }
            int kk = k0 + bkk;
            bv0 = make_float4(0.f, 0.f, 0.f, 0.f); bv1 = bv0;
            if (kk < IND) {
                bv0 = *(const float4*)&W[(size_t)kk * 256 + colBase + bc];
                bv1 = *(const float4*)&W[(size_t)kk * 256 + colBase + bc + 4];
            }
        }
        // MMA phase over buffer cur
#pragma unroll
        for (int ks = 0; ks < 16; ks += 8) {
            unsigned a[2][4];
#pragma unroll
            for (int mt = 0; mt < 2; mt++) {
                int m0 = warpM * 32 + mt * 16;
                a[mt][0] = As[cur][ks + q][m0 + p];
                a[mt][1] = As[cur][ks + q][m0 + p + 8];
                a[mt][2] = As[cur][ks + q + 4][m0 + p];
                a[mt][3] = As[cur][ks + q + 4][m0 + p + 8];
            }
#pragma unroll
            for (int nt = 0; nt < 8; nt++) {
                int n0 = warpN * 64 + nt * 8;
                unsigned b0 = Bs[cur][ks + q][n0 + p];
                unsigned b1 = Bs[cur][ks + q + 4][n0 + p];
#pragma unroll
                for (int mt = 0; mt < 2; mt++)
                    mma_tf32(acc[mt][nt][0], acc[mt][nt][1], acc[mt][nt][2], acc[mt][nt][3],
                             a[mt][0], a[mt][1], a[mt][2], a[mt][3], b0, b1);
            }
        }
        // store prefetched tile into the other buffer (safe: nobody reads it until after sync)
        if (hasNext) {
            int nb = cur ^ 1;
#pragma unroll
            for (int i = 0; i < 8; i++) As[nb][aklo + i][am] = f2tf32(avr[i]);
            Bs[nb][bkk][bc + 0] = f2tf32(bv0.x); Bs[nb][bkk][bc + 1] = f2tf32(bv0.y);
            Bs[nb][bkk][bc + 2] = f2tf32(bv0.z); Bs[nb][bkk][bc + 3] = f2tf32(bv0.w);
            Bs[nb][bkk][bc + 4] = f2tf32(bv1.x); Bs[nb][bkk][bc + 5] = f2tf32(bv1.y);
            Bs[nb][bkk][bc + 6] = f2tf32(bv1.z); Bs[nb][bkk][bc + 7] = f2tf32(bv1.w);
        }
        __syncthreads();
    }

    // bf16 store epilogue
#pragma unroll
    for (int mt = 0; mt < 2; mt++) {
        int r0 = rowBase + warpM * 32 + mt * 16 + p;
        int r1 = r0 + 8;
#pragma unroll
        for (int nt = 0; nt < 8; nt++) {
            int col = colBase + warpN * 64 + nt * 8 + 2 * q;
            if (r0 < NN) {
                __nv_bfloat162 v = __floats2bfloat162_rn(acc[mt][nt][0], acc[mt][nt][1]);
                *(__nv_bfloat162*)&g_xp[(size_t)r0 * 256 + col] = v;
            }
            if (r1 < NN) {
                __nv_bfloat162 v = __floats2bfloat162_rn(acc[mt][nt][2], acc[mt][nt][3]);
                *(__nv_bfloat162*)&g_xp[(size_t)r1 * 256 + col] = v;
            }
        }
    }

    // fused attention dots: this warp's 64-col slab is exactly head h;
    // each (row, head) has exactly one owner quad -> plain stores, no atomics.
    int h = blockIdx.x * 2 + warpN;
    float a_s0[8], a_s1[8], a_d0[8], a_d1[8];
#pragma unroll
    for (int nt = 0; nt < 8; nt++) {
        int cb = h * 64 + nt * 8 + 2 * q;
        a_s0[nt] = att_src[cb]; a_s1[nt] = att_src[cb + 1];
        a_d0[nt] = att_dst[cb]; a_d1[nt] = att_dst[cb + 1];
    }
#pragma unroll
    for (int mt = 0; mt < 2; mt++) {
        float sdA = 0.f, ddA = 0.f, sdB = 0.f, ddB = 0.f;
#pragma unroll
        for (int nt = 0; nt < 8; nt++) {
            sdA += acc[mt][nt][0] * a_s0[nt] + acc[mt][nt][1] * a_s1[nt];
            ddA += acc[mt][nt][0] * a_d0[nt] + acc[mt][nt][1] * a_d1[nt];
            sdB += acc[mt][nt][2] * a_s0[nt] + acc[mt][nt][3] * a_s1[nt];
            ddB += acc[mt][nt][2] * a_d0[nt] + acc[mt][nt][3] * a_d1[nt];
        }
#pragma unroll
        for (int off = 1; off < 4; off <<= 1) {
            sdA += __shfl_xor_sync(0xffffffffu, sdA, off);
            ddA += __shfl_xor_sync(0xffffffffu, ddA, off);
            sdB += __shfl_xor_sync(0xffffffffu, sdB, off);
            ddB += __shfl_xor_sync(0xffffffffu, ddB, off);
        }
        if (q == 0) {
            int rA = rowBase + warpM * 32 + mt * 16 + p;
            int rB = rA + 8;
            if (rA < NN) { g_asrc[rA * 4 + h] = sdA; g_adst[rA * 4 + h] = ddA; }
            if (rB < NN) { g_asrc[rB * 4 + h] = sdB; g_adst[rB * 4 + h] = ddB; }
        }
    }
}

// ---------------- K3: fused per-node softmax + aggregation + finalize + pool (R13 proven form) ----------------
// one warp per node; lane covers output cols (lane*2, lane*2+1)
__global__ __launch_bounds__(256) void k_node_csr(const void* __restrict__ batch,
                                                  const float* __restrict__ bias) {
    int n = (blockIdx.x * 256 + threadIdx.x) >> 5;
    int lane = threadIdx.x & 31;
    if (n >= NN) return;
    float4 ad = *(const float4*)&g_adst[n * 4];
    float4 an = *(const float4*)&g_asrc[n * 4];
    float se0 = __expf(lrelu(an.x + ad.x));
    float se1 = __expf(lrelu(an.y + ad.y));
    float se2 = __expf(lrelu(an.z + ad.z));
    float se3 = __expf(lrelu(an.w + ad.w));
    int o0 = g_off[n], o1 = g_off[n + 1];

    // loop1: per-edge exps (stored at binned positions, coalesced) + denominator
    float d0 = 0.f, d1 = 0.f, d2 = 0.f, d3 = 0.f;
    for (int e = o0 + lane; e < o1; e += 32) {
        int s = g_srcs[e];
        float4 as = *(const float4*)&g_asrc[s * 4];
        float e0 = __expf(lrelu(as.x + ad.x));
        float e1 = __expf(lrelu(as.y + ad.y));
        float e2 = __expf(lrelu(as.z + ad.z));
        float e3 = __expf(lrelu(as.w + ad.w));
        *(float4*)&g_ex[(size_t)e * 4] = make_float4(e0, e1, e2, e3);
        d0 += e0; d1 += e1; d2 += e2; d3 += e3;
    }
#pragma unroll
    for (int off = 16; off > 0; off >>= 1) {
        d0 += __shfl_xor_sync(0xffffffffu, d0, off);
        d1 += __shfl_xor_sync(0xffffffffu, d1, off);
        d2 += __shfl_xor_sync(0xffffffffu, d2, off);
        d3 += __shfl_xor_sync(0xffffffffu, d3, off);
    }
    float inv0 = __frcp_rn(d0 + se0);
    float inv1 = __frcp_rn(d1 + se1);
    float inv2 = __frcp_rn(d2 + se2);
    float inv3 = __frcp_rn(d3 + se3);

    int col = lane * 2;
    float acc0 = 0.f, acc1 = 0.f;
    // self-loop contribution
    {
        float a0 = se0 * inv0, a1 = se1 * inv1, a2 = se2 * inv2, a3 = se3 * inv3;
        const __nv_bfloat16* row = &g_xp[(size_t)n * 256];
        float2 p;
        p = bf2f(*(const unsigned*)&row[col]);        acc0 += a0 * p.x; acc1 += a0 * p.y;
        p = bf2f(*(const unsigned*)&row[64 + col]);   acc0 += a1 * p.x; acc1 += a1 * p.y;
        p = bf2f(*(const unsigned*)&row[128 + col]);  acc0 += a2 * p.x; acc1 += a2 * p.y;
        p = bf2f(*(const unsigned*)&row[192 + col]);  acc0 += a3 * p.x; acc1 += a3 * p.y;
    }
    // loop2: whole-warp per edge, 4-edge unroll for MLP
    int e = o0;
    for (; e + 4 <= o1; e += 4) {
        int s0 = g_srcs[e], s1 = g_srcs[e + 1], s2 = g_srcs[e + 2], s3 = g_srcs[e + 3];
        float4 xA = *(const float4*)&g_ex[(size_t)e * 4];
        float4 xB = *(const float4*)&g_ex[(size_t)(e + 1) * 4];
        float4 xC = *(const float4*)&g_ex[(size_t)(e + 2) * 4];
        float4 xD = *(const float4*)&g_ex[(size_t)(e + 3) * 4];
        const __nv_bfloat16* rA = &g_xp[(size_t)s0 * 256];
        const __nv_bfloat16* rB = &g_xp[(size_t)s1 * 256];
        const __nv_bfloat16* rC = &g_xp[(size_t)s2 * 256];
        const __nv_bfloat16* rD = &g_xp[(size_t)s3 * 256];
        unsigned uA0 = *(const unsigned*)&rA[col],       uA1 = *(const unsigned*)&rA[64 + col];
        unsigned uA2 = *(const unsigned*)&rA[128 + col], uA3 = *(const unsigned*)&rA[192 + col];
        unsigned uB0 = *(const unsigned*)&rB[col],       uB1 = *(const unsigned*)&rB[64 + col];
        unsigned uB2 = *(const unsigned*)&rB[128 + col], uB3 = *(const unsigned*)&rB[192 + col];
        unsigned uC0 = *(const unsigned*)&rC[col],       uC1 = *(const unsigned*)&rC[64 + col];
        unsigned uC2 = *(const unsigned*)&rC[128 + col], uC3 = *(const unsigned*)&rC[192 + col];
        unsigned uD0 = *(const unsigned*)&rD[col],       uD1 = *(const unsigned*)&rD[64 + col];
        unsigned uD2 = *(const unsigned*)&rD[128 + col], uD3 = *(const unsigned*)&rD[192 + col];
        float2 p;
        p = bf2f(uA0); acc0 += xA.x * inv0 * p.x; acc1 += xA.x * inv0 * p.y;
        p = bf2f(uA1); acc0 += xA.y * inv1 * p.x; acc1 += xA.y * inv1 * p.y;
        p = bf2f(uA2); acc0 += xA.z * inv2 * p.x; acc1 += xA.z * inv2 * p.y;
        p = bf2f(uA3); acc0 += xA.w * inv3 * p.x; acc1 += xA.w * inv3 * p.y;
        p = bf2f(uB0); acc0 += xB.x * inv0 * p.x; acc1 += xB.x * inv0 * p.y;
        p = bf2f(uB1); acc0 += xB.y * inv1 * p.x; acc1 += xB.y * inv1 * p.y;
        p = bf2f(uB2); acc0 += xB.z * inv2 * p.x; acc1 += xB.z * inv2 * p.y;
        p = bf2f(uB3); acc0 += xB.w * inv3 * p.x; acc1 += xB.w * inv3 * p.y;
        p = bf2f(uC0); acc0 += xC.x * inv0 * p.x; acc1 += xC.x * inv0 * p.y;
        p = bf2f(uC1); acc0 += xC.y * inv1 * p.x; acc1 += xC.y * inv1 * p.y;
        p = bf2f(uC2); acc0 += xC.z * inv2 * p.x; acc1 += xC.z * inv2 * p.y;
        p = bf2f(uC3); acc0 += xC.w * inv3 * p.x; acc1 += xC.w * inv3 * p.y;
        p = bf2f(uD0); acc0 += xD.x * inv0 * p.x; acc1 += xD.x * inv0 * p.y;
        p = bf2f(uD1); acc0 += xD.y * inv1 * p.x; acc1 += xD.y * inv1 * p.y;
        p = bf2f(uD2); acc0 += xD.z * inv2 * p.x; acc1 += xD.z * inv2 * p.y;
        p = bf2f(uD3); acc0 += xD.w * inv3 * p.x; acc1 += xD.w * inv3 * p.y;
    }
    for (; e < o1; e++) {
        int s = g_srcs[e];
        float4 ex = *(const float4*)&g_ex[(size_t)e * 4];
        float a0 = ex.x * inv0, a1 = ex.y * inv1, a2 = ex.z * inv2, a3 = ex.w * inv3;
        const __nv_bfloat16* row = &g_xp[(size_t)s * 256];
        float2 p;
        p = bf2f(*(const unsigned*)&row[col]);        acc0 += a0 * p.x; acc1 += a0 * p.y;
        p = bf2f(*(const unsigned*)&row[64 + col]);   acc0 += a1 * p.x; acc1 += a1 * p.y;
        p = bf2f(*(const unsigned*)&row[128 + col]);  acc0 += a2 * p.x; acc1 += a2 * p.y;
        p = bf2f(*(const unsigned*)&row[192 + col]);  acc0 += a3 * p.x; acc1 += a3 * p.y;
    }
    // head mean + bias + relu
    float r0 = fmaxf(acc0 * 0.25f + bias[col], 0.f);
    float r1 = fmaxf(acc1 * 0.25f + bias[col + 1], 0.f);
    int gph = ldidx(batch, n, g_b64, GG);
    red2(&g_pool[gph * 64 + col], r0, r1);
    if (lane == 0) atomicAdd(&g_cnt[gph], 1.0f);
}

// ---------------- K5: per-graph mean + MLP head + sigmoid ----------------
__global__ void k_head(const float* __restrict__ w1, const float* __restrict__ b1,
                       const float* __restrict__ w2, const float* __restrict__ b2,
                       float* __restrict__ out) {
    __shared__ float w1s[64 * 64];
    __shared__ float b1s[64];
    __shared__ float w2s[64];
    int t = threadIdx.x;
    for (int i = t; i < 64 * 64; i += 128) w1s[i] = w1[i];
    if (t < 64) { b1s[t] = b1[t]; w2s[t] = w2[t]; }
    __syncthreads();
    if (t < GG) {
        float cnt = fmaxf(g_cnt[t], 1.0f);
        float inv = 1.0f / cnt;
        float gv[64];
#pragma unroll
        for (int c = 0; c < 64; c++) gv[c] = g_pool[t * 64 + c] * inv;
        float z = b2[0];
        for (int k = 0; k < 64; k++) {
            float a = b1s[k];
#pragma unroll
            for (int c = 0; c < 64; c++) a += gv[c] * w1s[c * 64 + k];
            a = fmaxf(a, 0.f);
            z += a * w2s[k];
        }
        out[t] = 1.0f / (1.0f + expf(-z));
    }
}

// ---------------- launcher (gemm at launch #4 so ncu profiles it) ----------------
extern "C" void kernel_launch(void* const* d_in, const int* in_sizes, int n_in,
                              void* d_out, int out_size) {
    const float* x       = (const float*)d_in[0];
    const float* W       = (const float*)d_in[1];
    const float* att_src = (const float*)d_in[2];
    const float* att_dst = (const float*)d_in[3];
    const float* bias    = (const float*)d_in[4];
    const float* w1      = (const float*)d_in[5];
    const float* b1      = (const float*)d_in[6];
    const float* w2      = (const float*)d_in[7];
    const float* b2      = (const float*)d_in[8];
    const void*  ei      = d_in[9];
    const void*  bat     = d_in[10];

    k_detect<<<1, 256>>>((const int*)ei, (const int*)bat);
    k_zero<<<200, 512>>>();
    k_hist<<<(EE + 255) / 256, 256>>>(ei);
    dim3 gg(2, (NN + 127) / 128);
    k_gemm<<<gg, 256>>>(x, W, att_src, att_dst);   // launch #4 -> profiled
    k_scanA<<<NB, 1024>>>();
    k_scanB<<<1, 128>>>();
    k_scanC<<<NB, 1024>>>();
    k_scatter<<<(EE + 255) / 256, 256>>>(ei);
    k_node_csr<<<(NN * 32 + 255) / 256, 256>>>(bat, bias);
    k_head<<<1, 128>>>(w1, b1, w2, b2, (float*)d_out);
}

// round 17
// speedup vs baseline: 1.4160x; 1.1188x over previous
#include <cuda_runtime.h>
#include <cuda_bf16.h>
#include <cstdint>

#define NN 100000
#define EE 1600000
#define GG 128
#define IND 329
#define NEG 0.2f
#define NB 98          // ceil(NN/1024)

// ---------------- device scratch (no allocation allowed) ----------------
__device__ __align__(256) __nv_bfloat16 g_xp[(size_t)NN * 256];   // 51.2 MB bf16 features [N][H*C]
__device__ __align__(256) float g_asrc[NN * 4];
__device__ __align__(256) float g_adst[NN * 4];
__device__ __align__(256) float g_ex[(size_t)EE * 4];             // 25.6 MB per-edge exp values
__device__ __align__(256) int   g_srcs[EE];                       // 6.4 MB dst-binned src list
__device__ __align__(256) int   g_deg[NN];
__device__ __align__(256) int   g_off[NN + 1];
__device__ __align__(256) int   g_cursor[NN];
__device__ __align__(256) int   g_bsum[NB];
__device__ __align__(256) int   g_bsum2[NB];
__device__ __align__(256) float g_pool[GG * 64];
__device__ __align__(256) float g_cnt[GG];
__device__ int g_e64;   // 1 if edge_index is int64, 0 if int32
__device__ int g_b64;   // 1 if batch is int64, 0 if int32

// ---------------- small helpers ----------------
__device__ __forceinline__ float2 bf2f(unsigned u) {
    __nv_bfloat162 b = *reinterpret_cast<const __nv_bfloat162*>(&u);
    return __bfloat1622float2(b);
}
__device__ __forceinline__ unsigned fpack2(float lo, float hi) {
    __nv_bfloat162 b = __floats2bfloat162_rn(lo, hi);   // lo -> low 16 bits (k), hi -> high (k+1)
    return *reinterpret_cast<unsigned*>(&b);
}
__device__ __forceinline__ float lrelu(float x) { return x > 0.f ? x : NEG * x; }
__device__ __forceinline__ void red2(float* p, float a, float b) {
    asm volatile("red.global.add.v2.f32 [%0], {%1,%2};"
                 :: "l"(p), "f"(a), "f"(b) : "memory");
}
__device__ __forceinline__ void mma_bf16(float& c0, float& c1, float& c2, float& c3,
                                         unsigned a0, unsigned a1, unsigned a2, unsigned a3,
                                         unsigned b0, unsigned b1) {
    asm volatile("mma.sync.aligned.m16n8k16.row.col.f32.bf16.bf16.f32 "
                 "{%0,%1,%2,%3}, {%4,%5,%6,%7}, {%8,%9}, {%0,%1,%2,%3};"
                 : "+f"(c0), "+f"(c1), "+f"(c2), "+f"(c3)
                 : "r"(a0), "r"(a1), "r"(a2), "r"(a3), "r"(b0), "r"(b1));
}
// dtype-flexible index load, clamped to [0, lim-1]
__device__ __forceinline__ int ldidx(const void* p, long long i, int is64, int lim) {
    long long v = is64 ? ((const long long*)p)[i] : (long long)((const int*)p)[i];
    if (v < 0) v = 0;
    if (v >= lim) v = lim - 1;
    return (int)v;
}

// ---------------- K-1: dtype detector (int32 vs int64) ----------------
__global__ void k_detect(const int* __restrict__ ei_raw, const int* __restrict__ bat_raw) {
    __shared__ int nz_e, nz_b;
    int t = threadIdx.x;  // 256 threads
    if (t == 0) { nz_e = 0; nz_b = 0; }
    __syncthreads();
    if (ei_raw[2 * t + 1] != 0) atomicOr(&nz_e, 1);
    if (bat_raw[NN - 1 - 2 * t] != 0) atomicOr(&nz_b, 1);
    __syncthreads();
    if (t == 0) { g_e64 = nz_e ? 0 : 1; g_b64 = nz_b ? 0 : 1; }
}

// ---------------- K0: zero degree table + pool accumulators ----------------
__global__ void k_zero() {
    int i = blockIdx.x * blockDim.x + threadIdx.x;
    int stride = gridDim.x * blockDim.x;
    for (int j = i; j < NN; j += stride) g_deg[j] = 0;
    if (i < GG * 64) g_pool[i] = 0.f;
    if (i < GG) g_cnt[i] = 0.f;
}

// ---------------- CSR build: histogram ----------------
__global__ void k_hist(const void* __restrict__ ei) {
    int e = blockIdx.x * 256 + threadIdx.x;
    if (e >= EE) return;
    int d = ldidx(ei, (long long)EE + e, g_e64, NN);
    atomicAdd(&g_deg[d], 1);
}

// ---------------- CSR build: 3-phase multi-block exclusive scan ----------------
__global__ __launch_bounds__(1024) void k_scanA() {
    __shared__ int wsum[32];
    int b = blockIdx.x, tid = threadIdx.x;
    int lane = tid & 31, wid = tid >> 5;
    int idx = b * 1024 + tid;
    int v = (idx < NN) ? g_deg[idx] : 0;
    int inc = v;
#pragma unroll
    for (int off = 1; off < 32; off <<= 1) {
        int t = __shfl_up_sync(0xffffffffu, inc, off);
        if (lane >= off) inc += t;
    }
    if (lane == 31) wsum[wid] = inc;
    __syncthreads();
    if (wid == 0) {
        int x = wsum[lane];
        int iw = x;
#pragma unroll
        for (int off = 1; off < 32; off <<= 1) {
            int t = __shfl_up_sync(0xffffffffu, iw, off);
            if (lane >= off) iw += t;
        }
        wsum[lane] = iw - x;   // exclusive warp offset
    }
    __syncthreads();
    int excl = inc - v + wsum[wid];
    if (idx < NN) g_off[idx] = excl;         // block-local exclusive
    if (tid == 1023) g_bsum[b] = excl + v;   // block total
}

__global__ void k_scanB() {
    __shared__ int wsum[4];
    int t = threadIdx.x;   // 128 threads
    int lane = t & 31, wid = t >> 5;
    int v = (t < NB) ? g_bsum[t] : 0;
    int inc = v;
#pragma unroll
    for (int off = 1; off < 32; off <<= 1) {
        int x = __shfl_up_sync(0xffffffffu, inc, off);
        if (lane >= off) inc += x;
    }
    if (lane == 31) wsum[wid] = inc;
    __syncthreads();
    if (t == 0) {
        int run = 0;
#pragma unroll
        for (int i = 0; i < 4; i++) { int x = wsum[i]; wsum[i] = run; run += x; }
    }
    __syncthreads();
    if (t < NB) g_bsum2[t] = inc - v + wsum[wid];
}

__global__ __launch_bounds__(1024) void k_scanC() {
    int b = blockIdx.x, tid = threadIdx.x;
    int idx = b * 1024 + tid;
    if (idx < NN) {
        int o = g_off[idx] + g_bsum2[b];
        g_off[idx] = o;
        g_cursor[idx] = o;
    }
    if (idx == 0) g_off[NN] = EE;
}

// ---------------- CSR build: scatter srcs into dst bins ----------------
__global__ void k_scatter(const void* __restrict__ ei) {
    int e = blockIdx.x * 256 + threadIdx.x;
    if (e >= EE) return;
    int f = g_e64;
    int s = ldidx(ei, e, f, NN);
    int d = ldidx(ei, (long long)EE + e, f, NN);
    int p = atomicAdd(&g_cursor[d], 1);
    g_srcs[p] = s;
}

// ---------------- K1: BF16 tensor-core GEMM  xp = x @ W  (bf16 store)
// m16n8k16 bf16 mma: half the LDS traffic and half the MMA count of the tf32
// version (k-pairs packed in 32-bit words). Double-buffered smem + register
// prefetch, ONE sync per k-tile. + fused attention dots from fp32 accumulators.
#define SSTRIDE 136
__global__ __launch_bounds__(256, 2) void k_gemm(const float* __restrict__ x,
                                                 const float* __restrict__ W,
                                                 const float* __restrict__ att_src,
                                                 const float* __restrict__ att_dst) {
    __shared__ unsigned As[2][8][SSTRIDE];   // [k-word][m]  (k-word = 2 k-elems)
    __shared__ unsigned Bs[2][8][SSTRIDE];   // [k-word][n]
    int tid = threadIdx.x;
    int lane = tid & 31;
    int wid = tid >> 5;
    int warpM = wid & 3;
    int warpN = wid >> 2;
    int rowBase = blockIdx.y * 128;
    int colBase = blockIdx.x * 128;
    int p = lane >> 2;
    int q = lane & 3;

    float acc[2][8][4];
#pragma unroll
    for (int i = 0; i < 2; i++)
#pragma unroll
        for (int j = 0; j < 8; j++)
#pragma unroll
            for (int r = 0; r < 4; r++) acc[i][j][r] = 0.f;

    // A: thread -> row am, k-halves [aklo, aklo+8)
    int am = tid >> 1;
    int aklo = (tid & 1) * 8;
    int akw = (tid & 1) * 4;      // k-word base
    int arow = rowBase + am;
    // B: thread -> k-pair kp (rows 2kp, 2kp+1), 4 cols
    int kp = tid >> 5;            // 0..7
    int bc = (tid & 31) * 4;

    float avr[8];
    float4 bv0, bv1;

    // prologue: load + pack + store tile 0
#pragma unroll
    for (int i = 0; i < 8; i++) {
        int kk = aklo + i;
        avr[i] = (arow < NN && kk < IND) ? x[(size_t)arow * IND + kk] : 0.f;
    }
    bv0 = make_float4(0.f, 0.f, 0.f, 0.f); bv1 = bv0;
    {
        int r0 = 2 * kp, r1 = r0 + 1;
        if (r0 < IND) bv0 = *(const float4*)&W[(size_t)r0 * 256 + colBase + bc];
        if (r1 < IND) bv1 = *(const float4*)&W[(size_t)r1 * 256 + colBase + bc];
    }
#pragma unroll
    for (int i = 0; i < 4; i++) As[0][akw + i][am] = fpack2(avr[2 * i], avr[2 * i + 1]);
    Bs[0][kp][bc + 0] = fpack2(bv0.x, bv1.x);
    Bs[0][kp][bc + 1] = fpack2(bv0.y, bv1.y);
    Bs[0][kp][bc + 2] = fpack2(bv0.z, bv1.z);
    Bs[0][kp][bc + 3] = fpack2(bv0.w, bv1.w);
    __syncthreads();

    for (int kt = 0; kt < 21; kt++) {
        int cur = kt & 1;
        bool hasNext = (kt + 1 < 21);
        // prefetch tile kt+1 into registers (overlaps MMA phase)
        if (hasNext) {
            int k0 = (kt + 1) * 16;
#pragma unroll
            for (int i = 0; i < 8; i++) {
                int kk = k0 + aklo + i;
                avr[i] = (arow < NN && kk < IND) ? x[(size_t)arow * IND + kk] : 0.f;
            }
            int r0 = k0 + 2 * kp, r1 = r0 + 1;
            bv0 = make_float4(0.f, 0.f, 0.f, 0.f); bv1 = bv0;
            if (r0 < IND) bv0 = *(const float4*)&W[(size_t)r0 * 256 + colBase + bc];
            if (r1 < IND) bv1 = *(const float4*)&W[(size_t)r1 * 256 + colBase + bc];
        }
        // MMA phase over buffer cur: one m16n8k16 covers the whole k-tile
        {
            unsigned a[2][4];
#pragma unroll
            for (int mt = 0; mt < 2; mt++) {
                int m0 = warpM * 32 + mt * 16;
                a[mt][0] = As[cur][q][m0 + p];
                a[mt][1] = As[cur][q][m0 + p + 8];
                a[mt][2] = As[cur][q + 4][m0 + p];
                a[mt][3] = As[cur][q + 4][m0 + p + 8];
            }
#pragma unroll
            for (int nt = 0; nt < 8; nt++) {
                int n0 = warpN * 64 + nt * 8;
                unsigned b0 = Bs[cur][q][n0 + p];
                unsigned b1 = Bs[cur][q + 4][n0 + p];
#pragma unroll
                for (int mt = 0; mt < 2; mt++)
                    mma_bf16(acc[mt][nt][0], acc[mt][nt][1], acc[mt][nt][2], acc[mt][nt][3],
                             a[mt][0], a[mt][1], a[mt][2], a[mt][3], b0, b1);
            }
        }
        // store prefetched tile into the other buffer
        if (hasNext) {
            int nb = cur ^ 1;
#pragma unroll
            for (int i = 0; i < 4; i++) As[nb][akw + i][am] = fpack2(avr[2 * i], avr[2 * i + 1]);
            Bs[nb][kp][bc + 0] = fpack2(bv0.x, bv1.x);
            Bs[nb][kp][bc + 1] = fpack2(bv0.y, bv1.y);
            Bs[nb][kp][bc + 2] = fpack2(bv0.z, bv1.z);
            Bs[nb][kp][bc + 3] = fpack2(bv0.w, bv1.w);
        }
        __syncthreads();
    }

    // bf16 store epilogue (accumulator layout identical to tf32 version)
#pragma unroll
    for (int mt = 0; mt < 2; mt++) {
        int r0 = rowBase + warpM * 32 + mt * 16 + p;
        int r1 = r0 + 8;
#pragma unroll
        for (int nt = 0; nt < 8; nt++) {
            int col = colBase + warpN * 64 + nt * 8 + 2 * q;
            if (r0 < NN) {
                __nv_bfloat162 v = __floats2bfloat162_rn(acc[mt][nt][0], acc[mt][nt][1]);
                *(__nv_bfloat162*)&g_xp[(size_t)r0 * 256 + col] = v;
            }
            if (r1 < NN) {
                __nv_bfloat162 v = __floats2bfloat162_rn(acc[mt][nt][2], acc[mt][nt][3]);
                *(__nv_bfloat162*)&g_xp[(size_t)r1 * 256 + col] = v;
            }
        }
    }

    // fused attention dots: this warp's 64-col slab is exactly head h;
    // each (row, head) has exactly one owner quad -> plain stores, no atomics.
    int h = blockIdx.x * 2 + warpN;
    float a_s0[8], a_s1[8], a_d0[8], a_d1[8];
#pragma unroll
    for (int nt = 0; nt < 8; nt++) {
        int cb = h * 64 + nt * 8 + 2 * q;
        a_s0[nt] = att_src[cb]; a_s1[nt] = att_src[cb + 1];
        a_d0[nt] = att_dst[cb]; a_d1[nt] = att_dst[cb + 1];
    }
#pragma unroll
    for (int mt = 0; mt < 2; mt++) {
        float sdA = 0.f, ddA = 0.f, sdB = 0.f, ddB = 0.f;
#pragma unroll
        for (int nt = 0; nt < 8; nt++) {
            sdA += acc[mt][nt][0] * a_s0[nt] + acc[mt][nt][1] * a_s1[nt];
            ddA += acc[mt][nt][0] * a_d0[nt] + acc[mt][nt][1] * a_d1[nt];
            sdB += acc[mt][nt][2] * a_s0[nt] + acc[mt][nt][3] * a_s1[nt];
            ddB += acc[mt][nt][2] * a_d0[nt] + acc[mt][nt][3] * a_d1[nt];
        }
#pragma unroll
        for (int off = 1; off < 4; off <<= 1) {
            sdA += __shfl_xor_sync(0xffffffffu, sdA, off);
            ddA += __shfl_xor_sync(0xffffffffu, ddA, off);
            sdB += __shfl_xor_sync(0xffffffffu, sdB, off);
            ddB += __shfl_xor_sync(0xffffffffu, ddB, off);
        }
        if (q == 0) {
            int rA = rowBase + warpM * 32 + mt * 16 + p;
            int rB = rA + 8;
            if (rA < NN) { g_asrc[rA * 4 + h] = sdA; g_adst[rA * 4 + h] = ddA; }
            if (rB < NN) { g_asrc[rB * 4 + h] = sdB; g_adst[rB * 4 + h] = ddB; }
        }
    }
}

// ---------------- K3: fused per-node softmax + aggregation + finalize + pool (R13 proven form) ----------------
// one warp per node; lane covers output cols (lane*2, lane*2+1)
__global__ __launch_bounds__(256) void k_node_csr(const void* __restrict__ batch,
                                                  const float* __restrict__ bias) {
    int n = (blockIdx.x * 256 + threadIdx.x) >> 5;
    int lane = threadIdx.x & 31;
    if (n >= NN) return;
    float4 ad = *(const float4*)&g_adst[n * 4];
    float4 an = *(const float4*)&g_asrc[n * 4];
    float se0 = __expf(lrelu(an.x + ad.x));
    float se1 = __expf(lrelu(an.y + ad.y));
    float se2 = __expf(lrelu(an.z + ad.z));
    float se3 = __expf(lrelu(an.w + ad.w));
    int o0 = g_off[n], o1 = g_off[n + 1];

    // loop1: per-edge exps (stored at binned positions, coalesced) + denominator
    float d0 = 0.f, d1 = 0.f, d2 = 0.f, d3 = 0.f;
    for (int e = o0 + lane; e < o1; e += 32) {
        int s = g_srcs[e];
        float4 as = *(const float4*)&g_asrc[s * 4];
        float e0 = __expf(lrelu(as.x + ad.x));
        float e1 = __expf(lrelu(as.y + ad.y));
        float e2 = __expf(lrelu(as.z + ad.z));
        float e3 = __expf(lrelu(as.w + ad.w));
        *(float4*)&g_ex[(size_t)e * 4] = make_float4(e0, e1, e2, e3);
        d0 += e0; d1 += e1; d2 += e2; d3 += e3;
    }
#pragma unroll
    for (int off = 16; off > 0; off >>= 1) {
        d0 += __shfl_xor_sync(0xffffffffu, d0, off);
        d1 += __shfl_xor_sync(0xffffffffu, d1, off);
        d2 += __shfl_xor_sync(0xffffffffu, d2, off);
        d3 += __shfl_xor_sync(0xffffffffu, d3, off);
    }
    float inv0 = __frcp_rn(d0 + se0);
    float inv1 = __frcp_rn(d1 + se1);
    float inv2 = __frcp_rn(d2 + se2);
    float inv3 = __frcp_rn(d3 + se3);

    int col = lane * 2;
    float acc0 = 0.f, acc1 = 0.f;
    // self-loop contribution
    {
        float a0 = se0 * inv0, a1 = se1 * inv1, a2 = se2 * inv2, a3 = se3 * inv3;
        const __nv_bfloat16* row = &g_xp[(size_t)n * 256];
        float2 p;
        p = bf2f(*(const unsigned*)&row[col]);        acc0 += a0 * p.x; acc1 += a0 * p.y;
        p = bf2f(*(const unsigned*)&row[64 + col]);   acc0 += a1 * p.x; acc1 += a1 * p.y;
        p = bf2f(*(const unsigned*)&row[128 + col]);  acc0 += a2 * p.x; acc1 += a2 * p.y;
        p = bf2f(*(const unsigned*)&row[192 + col]);  acc0 += a3 * p.x; acc1 += a3 * p.y;
    }
    // loop2: whole-warp per edge, 4-edge unroll for MLP
    int e = o0;
    for (; e + 4 <= o1; e += 4) {
        int s0 = g_srcs[e], s1 = g_srcs[e + 1], s2 = g_srcs[e + 2], s3 = g_srcs[e + 3];
        float4 xA = *(const float4*)&g_ex[(size_t)e * 4];
        float4 xB = *(const float4*)&g_ex[(size_t)(e + 1) * 4];
        float4 xC = *(const float4*)&g_ex[(size_t)(e + 2) * 4];
        float4 xD = *(const float4*)&g_ex[(size_t)(e + 3) * 4];
        const __nv_bfloat16* rA = &g_xp[(size_t)s0 * 256];
        const __nv_bfloat16* rB = &g_xp[(size_t)s1 * 256];
        const __nv_bfloat16* rC = &g_xp[(size_t)s2 * 256];
        const __nv_bfloat16* rD = &g_xp[(size_t)s3 * 256];
        unsigned uA0 = *(const unsigned*)&rA[col],       uA1 = *(const unsigned*)&rA[64 + col];
        unsigned uA2 = *(const unsigned*)&rA[128 + col], uA3 = *(const unsigned*)&rA[192 + col];
        unsigned uB0 = *(const unsigned*)&rB[col],       uB1 = *(const unsigned*)&rB[64 + col];
        unsigned uB2 = *(const unsigned*)&rB[128 + col], uB3 = *(const unsigned*)&rB[192 + col];
        unsigned uC0 = *(const unsigned*)&rC[col],       uC1 = *(const unsigned*)&rC[64 + col];
        unsigned uC2 = *(const unsigned*)&rC[128 + col], uC3 = *(const unsigned*)&rC[192 + col];
        unsigned uD0 = *(const unsigned*)&rD[col],       uD1 = *(const unsigned*)&rD[64 + col];
        unsigned uD2 = *(const unsigned*)&rD[128 + col], uD3 = *(const unsigned*)&rD[192 + col];
        float2 p;
        p = bf2f(uA0); acc0 += xA.x * inv0 * p.x; acc1 += xA.x * inv0 * p.y;
        p = bf2f(uA1); acc0 += xA.y * inv1 * p.x; acc1 += xA.y * inv1 * p.y;
        p = bf2f(uA2); acc0 += xA.z * inv2 * p.x; acc1 += xA.z * inv2 * p.y;
        p = bf2f(uA3); acc0 += xA.w * inv3 * p.x; acc1 += xA.w * inv3 * p.y;
        p = bf2f(uB0); acc0 += xB.x * inv0 * p.x; acc1 += xB.x * inv0 * p.y;
        p = bf2f(uB1); acc0 += xB.y * inv1 * p.x; acc1 += xB.y * inv1 * p.y;
        p = bf2f(uB2); acc0 += xB.z * inv2 * p.x; acc1 += xB.z * inv2 * p.y;
        p = bf2f(uB3); acc0 += xB.w * inv3 * p.x; acc1 += xB.w * inv3 * p.y;
        p = bf2f(uC0); acc0 += xC.x * inv0 * p.x; acc1 += xC.x * inv0 * p.y;
        p = bf2f(uC1); acc0 += xC.y * inv1 * p.x; acc1 += xC.y * inv1 * p.y;
        p = bf2f(uC2); acc0 += xC.z * inv2 * p.x; acc1 += xC.z * inv2 * p.y;
        p = bf2f(uC3); acc0 += xC.w * inv3 * p.x; acc1 += xC.w * inv3 * p.y;
        p = bf2f(uD0); acc0 += xD.x * inv0 * p.x; acc1 += xD.x * inv0 * p.y;
        p = bf2f(uD1); acc0 += xD.y * inv1 * p.x; acc1 += xD.y * inv1 * p.y;
        p = bf2f(uD2); acc0 += xD.z * inv2 * p.x; acc1 += xD.z * inv2 * p.y;
        p = bf2f(uD3); acc0 += xD.w * inv3 * p.x; acc1 += xD.w * inv3 * p.y;
    }
    for (; e < o1; e++) {
        int s = g_srcs[e];
        float4 ex = *(const float4*)&g_ex[(size_t)e * 4];
        float a0 = ex.x * inv0, a1 = ex.y * inv1, a2 = ex.z * inv2, a3 = ex.w * inv3;
        const __nv_bfloat16* row = &g_xp[(size_t)s * 256];
        float2 p;
        p = bf2f(*(const unsigned*)&row[col]);        acc0 += a0 * p.x; acc1 += a0 * p.y;
        p = bf2f(*(const unsigned*)&row[64 + col]);   acc0 += a1 * p.x; acc1 += a1 * p.y;
        p = bf2f(*(const unsigned*)&row[128 + col]);  acc0 += a2 * p.x; acc1 += a2 * p.y;
        p = bf2f(*(const unsigned*)&row[192 + col]);  acc0 += a3 * p.x; acc1 += a3 * p.y;
    }
    // head mean + bias + relu
    float r0 = fmaxf(acc0 * 0.25f + bias[col], 0.f);
    float r1 = fmaxf(acc1 * 0.25f + bias[col + 1], 0.f);
    int gph = ldidx(batch, n, g_b64, GG);
    red2(&g_pool[gph * 64 + col], r0, r1);
    if (lane == 0) atomicAdd(&g_cnt[gph], 1.0f);
}

// ---------------- K5: per-graph mean + MLP head + sigmoid ----------------
__global__ void k_head(const float* __restrict__ w1, const float* __restrict__ b1,
                       const float* __restrict__ w2, const float* __restrict__ b2,
                       float* __restrict__ out) {
    __shared__ float w1s[64 * 64];
    __shared__ float b1s[64];
    __shared__ float w2s[64];
    int t = threadIdx.x;
    for (int i = t; i < 64 * 64; i += 128) w1s[i] = w1[i];
    if (t < 64) { b1s[t] = b1[t]; w2s[t] = w2[t]; }
    __syncthreads();
    if (t < GG) {
        float cnt = fmaxf(g_cnt[t], 1.0f);
        float inv = 1.0f / cnt;
        float gv[64];
#pragma unroll
        for (int c = 0; c < 64; c++) gv[c] = g_pool[t * 64 + c] * inv;
        float z = b2[0];
        for (int k = 0; k < 64; k++) {
            float a = b1s[k];
#pragma unroll
            for (int c = 0; c < 64; c++) a += gv[c] * w1s[c * 64 + k];
            a = fmaxf(a, 0.f);
            z += a * w2s[k];
        }
        out[t] = 1.0f / (1.0f + expf(-z));
    }
}

// ---------------- launcher (gemm at launch #4 so ncu profiles it) ----------------
extern "C" void kernel_launch(void* const* d_in, const int* in_sizes, int n_in,
                              void* d_out, int out_size) {
    const float* x       = (const float*)d_in[0];
    const float* W       = (const float*)d_in[1];
    const float* att_src = (const float*)d_in[2];
    const float* att_dst = (const float*)d_in[3];
    const float* bias    = (const float*)d_in[4];
    const float* w1      = (const float*)d_in[5];
    const float* b1      = (const float*)d_in[6];
    const float* w2      = (const float*)d_in[7];
    const float* b2      = (const float*)d_in[8];
    const void*  ei      = d_in[9];
    const void*  bat     = d_in[10];

    k_detect<<<1, 256>>>((const int*)ei, (const int*)bat);
    k_zero<<<200, 512>>>();
    k_hist<<<(EE + 255) / 256, 256>>>(ei);
    dim3 gg(2, (NN + 127) / 128);
    k_gemm<<<gg, 256>>>(x, W, att_src, att_dst);   // launch #4 -> profiled
    k_scanA<<<NB, 1024>>>();
    k_scanB<<<1, 128>>>();
    k_scanC<<<NB, 1024>>>();
    k_scatter<<<(EE + 255) / 256, 256>>>(ei);
    k_node_csr<<<(NN * 32 + 255) / 256, 256>>>(bat, bias);
    k_head<<<1, 128>>>(w1, b1, w2, b2, (float*)d_out);
}